// round 4
// baseline (speedup 1.0000x reference)
#include <cuda_runtime.h>
#include <cuda_fp16.h>
#include <cstdint>

// ============================================================================
// RBFEuclidean: out[b,u] = ||x_b||^2 - 2*(x@w)[b,u] + ||w_u||^2
//   x: [65536, 256] fp32, w: [256, 1024] fp32, out: [65536, 1024] fp32
//
// Generic-sm_103 tensor path: mma.sync.m16n8k16 fp16/fp32-accum + ldmatrix.
// This round: conv_x fused INTO the GEMM (A loaded as raw fp32, converted
// to swizzled fp16 smem in-kernel; row norms reduced in-kernel). Only 2
// kernels remain: conv_w (tiny) + fused GEMM.
// ============================================================================

#define MB_ 65536
#define KF_ 256
#define NU_ 1024
#define BM 128
#define BN 128
#define BK 64
#define NCH (KF_ / BK)        // 4 k-chunks

// ---- smem layout ----
#define S_RAWA  0             // 128 x 64 fp32 = 32KB (single buffer)
#define S_A16   32768         // 128 x 64 fp16 swizzled = 16KB (single buffer)
#define S_B     49152         // 2 x (128 x 64 fp16 swizzled) = 32KB
#define S_XSQ   81920         // 128 floats
#define SMEM_TOTAL (81920 + 512)   // 82432 -> 2 CTAs/SM

// ---- device scratch (no allocations allowed) ----
__device__ __half g_wh[(size_t)NU_ * KF_];   // w transposed fp16 [u][k]
__device__ float  g_wsq[NU_];

// ---- PTX helpers (generic sm_80+ only) ----
__device__ __forceinline__ uint32_t smem_to_u32(const void* p) {
    uint32_t a;
    asm("{ .reg .u64 t; cvta.to.shared.u64 t, %1; cvt.u32.u64 %0, t; }"
        : "=r"(a) : "l"(p));
    return a;
}

#define CP_ASYNC16(saddr, gptr) \
    asm volatile("cp.async.cg.shared.global [%0], [%1], 16;" \
        :: "r"(saddr), "l"(gptr) : "memory")
#define CP_COMMIT() asm volatile("cp.async.commit_group;" ::: "memory")
#define CP_WAIT0()  asm volatile("cp.async.wait_group 0;" ::: "memory")

__device__ __forceinline__ void ldmatrix_x4(uint32_t& r0, uint32_t& r1,
                                            uint32_t& r2, uint32_t& r3,
                                            uint32_t addr) {
    asm volatile("ldmatrix.sync.aligned.m8n8.x4.shared.b16 {%0,%1,%2,%3}, [%4];"
        : "=r"(r0), "=r"(r1), "=r"(r2), "=r"(r3) : "r"(addr));
}

__device__ __forceinline__ void mma_16816(float* c, const uint32_t* a,
                                          const uint32_t* b) {
    asm volatile(
        "mma.sync.aligned.m16n8k16.row.col.f32.f16.f16.f32 "
        "{%0,%1,%2,%3}, {%4,%5,%6,%7}, {%8,%9}, {%0,%1,%2,%3};"
        : "+f"(c[0]), "+f"(c[1]), "+f"(c[2]), "+f"(c[3])
        : "r"(a[0]), "r"(a[1]), "r"(a[2]), "r"(a[3]), "r"(b[0]), "r"(b[1]));
}

// ============================================================================
// Pre-pass: w fp32 [k][u] -> fp16 transposed [u][k] + col norms (1MB, ~4us)
// ============================================================================
__global__ __launch_bounds__(256) void conv_w_kernel(const float* __restrict__ w) {
    int n = blockIdx.x * 256 + threadIdx.x;  // 0..1023
    float s = 0.0f;
    size_t ob = (size_t)n * KF_;
#pragma unroll 4
    for (int k = 0; k < KF_; k++) {
        float f = w[(size_t)k * NU_ + n];
        g_wh[ob + k] = __float2half_rn(f);
        s += f * f;
    }
    g_wsq[n] = s;
}

// ============================================================================
// Fused GEMM: A converted fp32->fp16 in-kernel, row norms in-kernel,
// epilogue out = xsq[m] + wsq[n] - 2*cross.
// CTA = 128x128 tile, 256 threads (8 warps = 2(m) x 4(n)), warp = 64x32.
// ============================================================================
__global__ __launch_bounds__(256, 2) void rbf_fused_kernel(
        const float* __restrict__ x, float* __restrict__ out) {
    extern __shared__ char smem[];
    uint32_t sbase = smem_to_u32(smem);
    float* xsq_s = (float*)(smem + S_XSQ);

    int tid = threadIdx.x;
    int wid = tid >> 5;
    int lane = tid & 31;
    int warp_m = wid & 1;
    int warp_n = wid >> 1;

    int bx = blockIdx.x;     // n fastest -> 8 consecutive CTAs share A (L2)
    int m0 = (bx >> 3) * BM;
    int n0 = (bx & 7) * BN;

    if (tid < 128) xsq_s[tid] = 0.0f;

    // ---- loader index precompute ----
    // B (fp16): vectors v = tid + i*256, i<4; r=v>>3, cc=v&7 (16B chunks)
    int br_ = tid >> 3;
    int bcc = tid & 7;
    // A raw (fp32): vectors v = tid + i*256, i<8; r=v>>4, cp=v&15
    int ar_ = tid >> 4;      // rows advance by 16 per i
    int acp = tid & 15;

    auto load_chunk = [&](int c) {
        int k0 = c * BK;
        // raw A fp32: 128 rows x 256B, linear
#pragma unroll
        for (int i = 0; i < 8; i++) {
            int r = ar_ + i * 16;
            CP_ASYNC16(sbase + S_RAWA + (uint32_t)(r * 256 + acp * 16),
                       x + (size_t)(m0 + r) * KF_ + k0 + acp * 4);
        }
        // B fp16 swizzled
        uint32_t sB = sbase + S_B + (uint32_t)(c & 1) * 16384;
#pragma unroll
        for (int i = 0; i < 4; i++) {
            int r = br_ + i * 32;
            uint32_t soff = (uint32_t)(r * 128 + ((bcc ^ (r & 7)) << 4));
            CP_ASYNC16(sB + soff, g_wh + (size_t)(n0 + r) * KF_ + k0 + bcc * 8);
        }
        CP_COMMIT();
    };

    float acc[4][4][4];
#pragma unroll
    for (int a = 0; a < 4; a++)
#pragma unroll
        for (int b = 0; b < 4; b++)
#pragma unroll
            for (int c = 0; c < 4; c++) acc[a][b][c] = 0.0f;

    // ldmatrix lane addressing (swizzle xor is lane&7)
    uint32_t arow = (uint32_t)(warp_m * 64 + (lane & 15));
    uint32_t ahi  = (uint32_t)(lane >> 4);
    uint32_t brow = (uint32_t)(warp_n * 32 + ((lane >> 4) & 1) * 8 + (lane & 7));
    uint32_t bkbit = (uint32_t)((lane >> 3) & 1);
    uint32_t lxor  = (uint32_t)(lane & 7);

    load_chunk(0);

#pragma unroll
    for (int c = 0; c < NCH; c++) {
        CP_WAIT0();
        __syncthreads();          // loads visible; prior compute done

        // ---- convert A raw fp32 -> swizzled fp16, accumulate row norms ----
#pragma unroll
        for (int i = 0; i < 8; i++) {
            int r = ar_ + i * 16;
            float4 f = *(const float4*)(smem + S_RAWA + r * 256 + acp * 16);
            __half2 h01 = __floats2half2_rn(f.x, f.y);
            __half2 h23 = __floats2half2_rn(f.z, f.w);
            uint32_t sw = (uint32_t)(r * 128 + (((acp >> 1) ^ (r & 7)) << 4)
                                     + (acp & 1) * 8);
            uint2 hv;
            hv.x = *(uint32_t*)&h01;
            hv.y = *(uint32_t*)&h23;
            *(uint2*)(smem + S_A16 + sw) = hv;
            float ss = f.x * f.x + f.y * f.y + f.z * f.z + f.w * f.w;
            ss += __shfl_xor_sync(0xFFFFFFFFu, ss, 1);
            ss += __shfl_xor_sync(0xFFFFFFFFu, ss, 2);
            ss += __shfl_xor_sync(0xFFFFFFFFu, ss, 4);
            ss += __shfl_xor_sync(0xFFFFFFFFu, ss, 8);
            if ((lane & 15) == 0) atomicAdd(&xsq_s[r], ss);
        }
        __syncthreads();          // A16 visible; raw consumed

        if (c + 1 < NCH) load_chunk(c + 1);

        uint32_t sA = sbase + S_A16;
        uint32_t sB = sbase + S_B + (uint32_t)(c & 1) * 16384;

#pragma unroll
        for (int ks = 0; ks < 4; ks++) {
            uint32_t a[4][4];
            uint32_t b[4][2];
#pragma unroll
            for (int mi = 0; mi < 4; mi++) {
                uint32_t addr = sA + (arow + 16 * mi) * 128
                              + (((2 * ks + ahi) ^ lxor) << 4);
                ldmatrix_x4(a[mi][0], a[mi][1], a[mi][2], a[mi][3], addr);
            }
#pragma unroll
            for (int jj = 0; jj < 2; jj++) {
                uint32_t r0, r1, r2, r3;
                uint32_t addr = sB + (brow + 16 * jj) * 128
                              + (((2 * ks + bkbit) ^ lxor) << 4);
                ldmatrix_x4(r0, r1, r2, r3, addr);
                b[2 * jj][0] = r0; b[2 * jj][1] = r1;
                b[2 * jj + 1][0] = r2; b[2 * jj + 1][1] = r3;
            }
#pragma unroll
            for (int mi = 0; mi < 4; mi++)
#pragma unroll
                for (int nj = 0; nj < 4; nj++)
                    mma_16816(acc[mi][nj], a[mi], b[nj]);
        }
    }

    // ---- epilogue: out = xsq[m] + wsq[n] - 2*cross ----
    // xsq atomics all landed before the last pre-compute barrier.
    int g = lane >> 2;
    int q = lane & 3;
#pragma unroll
    for (int mi = 0; mi < 4; mi++) {
        int rloc = warp_m * 64 + mi * 16 + g;
        int m_lo = m0 + rloc;
        float xs0 = xsq_s[rloc];
        float xs1 = xsq_s[rloc + 8];
        float* op0 = out + (size_t)m_lo * NU_;
        float* op1 = out + (size_t)(m_lo + 8) * NU_;
#pragma unroll
        for (int nj = 0; nj < 4; nj++) {
            int n = n0 + warp_n * 32 + nj * 8 + q * 2;
            float w0 = g_wsq[n];
            float w1 = g_wsq[n + 1];
            float2 o0, o1;
            o0.x = xs0 + w0 - 2.0f * acc[mi][nj][0];
            o0.y = xs0 + w1 - 2.0f * acc[mi][nj][1];
            o1.x = xs1 + w0 - 2.0f * acc[mi][nj][2];
            o1.y = xs1 + w1 - 2.0f * acc[mi][nj][3];
            *(float2*)(op0 + n) = o0;
            *(float2*)(op1 + n) = o1;
        }
    }
}

// ============================================================================
// Launch: just 2 kernels now (conv_w tiny, then fused GEMM)
// ============================================================================
extern "C" void kernel_launch(void* const* d_in, const int* in_sizes, int n_in,
                              void* d_out, int out_size) {
    const float* x = (const float*)d_in[0];
    const float* w = (const float*)d_in[1];
    float* out = (float*)d_out;

    conv_w_kernel<<<NU_ / 256, 256>>>(w);

    cudaFuncSetAttribute(rbf_fused_kernel,
                         cudaFuncAttributeMaxDynamicSharedMemorySize, SMEM_TOTAL);
    int grid = (MB_ / BM) * (NU_ / BN);  // 512 * 8 = 4096
    rbf_fused_kernel<<<grid, 256, SMEM_TOTAL>>>(x, out);
}

// round 5
// speedup vs baseline: 1.9262x; 1.9262x over previous
#include <cuda_runtime.h>
#include <cuda_fp16.h>
#include <cstdint>

// ============================================================================
// RBFEuclidean: out[b,u] = ||x_b||^2 - 2*(x@w)[b,u] + ||w_u||^2
//   x: [65536, 256] fp32, w: [256, 1024] fp32, out: [65536, 1024] fp32
// R5: revert A-fusion; fast smem-transpose conv_w; GEMM retiled to 128x64
// CTAs (128 thr, 4 warps) -> 4 CTAs/SM for cross-CTA phase overlap.
// ============================================================================

#define MB_ 65536
#define KF_ 256
#define NU_ 1024
#define BM 128
#define BN 64
#define BK 64
#define NCH (KF_ / BK)          // 4 k-chunks
#define A_STAGE 16384           // 128 x 64 fp16
#define B_STAGE 8192            // 64 x 64 fp16
#define STAGE_BYTES (A_STAGE + B_STAGE)     // 24KB
#define SMEM_TOTAL (2 * STAGE_BYTES)        // 48KB -> 4 CTAs/SM

// ---- device scratch ----
__device__ __half g_xh[(size_t)MB_ * KF_];   // x fp16 [b][k]
__device__ __half g_wh[(size_t)NU_ * KF_];   // w fp16 transposed [u][k]
__device__ float  g_xsq[MB_];
__device__ float  g_wsq[NU_];

// ---- PTX helpers (generic sm_80+) ----
__device__ __forceinline__ uint32_t smem_to_u32(const void* p) {
    uint32_t a;
    asm("{ .reg .u64 t; cvta.to.shared.u64 t, %1; cvt.u32.u64 %0, t; }"
        : "=r"(a) : "l"(p));
    return a;
}

#define CP_ASYNC16(saddr, gptr) \
    asm volatile("cp.async.cg.shared.global [%0], [%1], 16;" \
        :: "r"(saddr), "l"(gptr) : "memory")
#define CP_COMMIT() asm volatile("cp.async.commit_group;" ::: "memory")
#define CP_WAIT1()  asm volatile("cp.async.wait_group 1;" ::: "memory")
#define CP_WAIT0()  asm volatile("cp.async.wait_group 0;" ::: "memory")

__device__ __forceinline__ void ldmatrix_x4(uint32_t& r0, uint32_t& r1,
                                            uint32_t& r2, uint32_t& r3,
                                            uint32_t addr) {
    asm volatile("ldmatrix.sync.aligned.m8n8.x4.shared.b16 {%0,%1,%2,%3}, [%4];"
        : "=r"(r0), "=r"(r1), "=r"(r2), "=r"(r3) : "r"(addr));
}

__device__ __forceinline__ void mma_16816(float* c, const uint32_t* a,
                                          const uint32_t* b) {
    asm volatile(
        "mma.sync.aligned.m16n8k16.row.col.f32.f16.f16.f32 "
        "{%0,%1,%2,%3}, {%4,%5,%6,%7}, {%8,%9}, {%0,%1,%2,%3};"
        : "+f"(c[0]), "+f"(c[1]), "+f"(c[2]), "+f"(c[3])
        : "r"(a[0]), "r"(a[1]), "r"(a[2]), "r"(a[3]), "r"(b[0]), "r"(b[1]));
}

// ============================================================================
// conv_x: x fp32 -> fp16 + row norms. One warp per row. (~14us, DRAM floor)
// ============================================================================
__global__ __launch_bounds__(256) void conv_x_kernel(const float* __restrict__ x) {
    int row = blockIdx.x * 8 + (threadIdx.x >> 5);
    int lane = threadIdx.x & 31;
    size_t base = (size_t)row * KF_ + lane * 8;
    float4 f0 = *(const float4*)(x + base);
    float4 f1 = *(const float4*)(x + base + 4);
    __half2 h[4];
    h[0] = __floats2half2_rn(f0.x, f0.y);
    h[1] = __floats2half2_rn(f0.z, f0.w);
    h[2] = __floats2half2_rn(f1.x, f1.y);
    h[3] = __floats2half2_rn(f1.z, f1.w);
    *(uint4*)(g_xh + base) = *(uint4*)h;
    float s = f0.x*f0.x + f0.y*f0.y + f0.z*f0.z + f0.w*f0.w
            + f1.x*f1.x + f1.y*f1.y + f1.z*f1.z + f1.w*f1.w;
#pragma unroll
    for (int o = 16; o; o >>= 1) s += __shfl_xor_sync(0xFFFFFFFFu, s, o);
    if (lane == 0) g_xsq[row] = s;
}

// ============================================================================
// conv_w: w fp32 [k][u] -> fp16 [u][k] via smem transpose, + col norms.
// 16 blocks x 256 threads; block handles 64 u-columns, all 256 k.
// Coalesced global reads AND writes.
// ============================================================================
__global__ __launch_bounds__(256) void conv_w_kernel(const float* __restrict__ w) {
    __shared__ __half sh[64][264];   // 264: 16B-aligned rows, modest conflicts
    __shared__ float swsq[64];
    int t = threadIdx.x;
    int u0 = blockIdx.x * 64;
    int uu = t & 63;
    int kk0 = t >> 6;                // 0..3
    if (t < 64) swsq[t] = 0.0f;
    __syncthreads();
    float part = 0.0f;
#pragma unroll 4
    for (int i = 0; i < 64; i++) {
        int k = kk0 + i * 4;
        float f = w[(size_t)k * NU_ + u0 + uu];   // coalesced across t
        sh[uu][k] = __float2half_rn(f);
        part += f * f;
    }
    atomicAdd(&swsq[uu], part);
    __syncthreads();
    // write out: thread t -> row u = t>>2, quarter q = t&3 (64 fp16 = 128B)
    int u = t >> 2, q = t & 3;
    const __half* src = &sh[u][q * 64];
    float4* dst = (float4*)(g_wh + (size_t)(u0 + u) * KF_ + q * 64);
#pragma unroll
    for (int j = 0; j < 8; j++)
        dst[j] = *(const float4*)(src + j * 8);
    if (t < 64) g_wsq[u0 + t] = swsq[t];
}

// ============================================================================
// GEMM + fused epilogue. CTA = 128x64 tile, 128 threads (4 warps = 2m x 2n),
// warp = 64x32. 2-stage cp.async double buffer. 4 CTAs/SM.
// ============================================================================
__global__ __launch_bounds__(128, 4) void rbf_gemm_kernel(float* __restrict__ out) {
    extern __shared__ char smem[];
    uint32_t sbase = smem_to_u32(smem);

    int tid = threadIdx.x;
    int wid = tid >> 5;
    int lane = tid & 31;
    int warp_m = wid & 1;    // 0..1 -> m offset 0/64
    int warp_n = wid >> 1;   // 0..1 -> n offset 0/32

    int bx = blockIdx.x;     // n fastest: 16 consecutive CTAs share A m-tile
    int m0 = (bx >> 4) * BM;
    int n0 = (bx & 15) * BN;

    // loader indices (128 threads): vectors v = tid + i*128; r=v>>3, cc=v&7
    int lr = tid >> 3;       // 0..15, rows advance by 16 per i
    int lcc = tid & 7;

    float acc[4][4][4];
#pragma unroll
    for (int a = 0; a < 4; a++)
#pragma unroll
        for (int b = 0; b < 4; b++)
#pragma unroll
            for (int c = 0; c < 4; c++) acc[a][b][c] = 0.0f;

    // ldmatrix lane addressing (swizzle xor = lane&7)
    uint32_t arow = (uint32_t)(warp_m * 64 + (lane & 15));
    uint32_t ahi  = (uint32_t)(lane >> 4);
    uint32_t brow = (uint32_t)(warp_n * 32 + ((lane >> 4) & 1) * 8 + (lane & 7));
    uint32_t bkbit = (uint32_t)((lane >> 3) & 1);
    uint32_t lxor  = (uint32_t)(lane & 7);

    auto load_chunk = [&](int c, int stage) {
        int k0 = c * BK;
        uint32_t sA = sbase + stage * STAGE_BYTES;
        uint32_t sB = sA + A_STAGE;
        // A: 128 rows x 64k = 1024 vec16, 8 per thread
#pragma unroll
        for (int i = 0; i < 8; i++) {
            int r = lr + i * 16;
            uint32_t soff = (uint32_t)(r * 128 + ((lcc ^ (r & 7)) << 4));
            CP_ASYNC16(sA + soff, g_xh + (size_t)(m0 + r) * KF_ + k0 + lcc * 8);
        }
        // B: 64 rows x 64k = 512 vec16, 4 per thread
#pragma unroll
        for (int i = 0; i < 4; i++) {
            int r = lr + i * 16;
            uint32_t soff = (uint32_t)(r * 128 + ((lcc ^ (r & 7)) << 4));
            CP_ASYNC16(sB + soff, g_wh + (size_t)(n0 + r) * KF_ + k0 + lcc * 8);
        }
        CP_COMMIT();
    };

    load_chunk(0, 0);

#pragma unroll
    for (int c = 0; c < NCH; c++) {
        if (c + 1 < NCH) {
            load_chunk(c + 1, (c + 1) & 1);
            CP_WAIT1();                 // chunk c arrived (c+1 still in flight)
        } else {
            CP_WAIT0();
        }
        __syncthreads();

        uint32_t sA = sbase + (c & 1) * STAGE_BYTES;
        uint32_t sB = sA + A_STAGE;

#pragma unroll
        for (int ks = 0; ks < 4; ks++) {
            uint32_t a[4][4];
            uint32_t b[4][2];
#pragma unroll
            for (int mi = 0; mi < 4; mi++) {
                uint32_t addr = sA + (arow + 16 * mi) * 128
                              + (((2 * ks + ahi) ^ lxor) << 4);
                ldmatrix_x4(a[mi][0], a[mi][1], a[mi][2], a[mi][3], addr);
            }
#pragma unroll
            for (int jj = 0; jj < 2; jj++) {
                uint32_t r0, r1, r2, r3;
                uint32_t addr = sB + (brow + 16 * jj) * 128
                              + (((2 * ks + bkbit) ^ lxor) << 4);
                ldmatrix_x4(r0, r1, r2, r3, addr);
                b[2 * jj][0] = r0; b[2 * jj][1] = r1;
                b[2 * jj + 1][0] = r2; b[2 * jj + 1][1] = r3;
            }
#pragma unroll
            for (int mi = 0; mi < 4; mi++)
#pragma unroll
                for (int nj = 0; nj < 4; nj++)
                    mma_16816(acc[mi][nj], a[mi], b[nj]);
        }
        __syncthreads();
    }

    // ---- epilogue: out = xsq[m] + wsq[n] - 2*cross ----
    int g = lane >> 2;
    int q = lane & 3;
#pragma unroll
    for (int mi = 0; mi < 4; mi++) {
        int m_lo = m0 + warp_m * 64 + mi * 16 + g;
        float xs0 = g_xsq[m_lo];
        float xs1 = g_xsq[m_lo + 8];
        float* op0 = out + (size_t)m_lo * NU_;
        float* op1 = out + (size_t)(m_lo + 8) * NU_;
#pragma unroll
        for (int nj = 0; nj < 4; nj++) {
            int n = n0 + warp_n * 32 + nj * 8 + q * 2;
            float w0 = g_wsq[n];
            float w1 = g_wsq[n + 1];
            float2 o0, o1;
            o0.x = xs0 + w0 - 2.0f * acc[mi][nj][0];
            o0.y = xs0 + w1 - 2.0f * acc[mi][nj][1];
            o1.x = xs1 + w0 - 2.0f * acc[mi][nj][2];
            o1.y = xs1 + w1 - 2.0f * acc[mi][nj][3];
            *(float2*)(op0 + n) = o0;
            *(float2*)(op1 + n) = o1;
        }
    }
}

// ============================================================================
// Launch
// ============================================================================
extern "C" void kernel_launch(void* const* d_in, const int* in_sizes, int n_in,
                              void* d_out, int out_size) {
    const float* x = (const float*)d_in[0];
    const float* w = (const float*)d_in[1];
    float* out = (float*)d_out;

    conv_w_kernel<<<NU_ / 64, 256>>>(w);
    conv_x_kernel<<<MB_ / 8, 256>>>(x);

    cudaFuncSetAttribute(rbf_gemm_kernel,
                         cudaFuncAttributeMaxDynamicSharedMemorySize, SMEM_TOTAL);
    int grid = (MB_ / BM) * (NU_ / BN);  // 512 * 16 = 8192
    rbf_gemm_kernel<<<grid, 128, SMEM_TOTAL>>>(out);
}